// round 4
// baseline (speedup 1.0000x reference)
#include <cuda_runtime.h>
#include <cuda_bf16.h>
#include <math.h>

// LocalPearsonDepthLoss — one warp per TWO patches.
//   Lane l reads column l of each 32-float row (coalesced 128B). Both patches'
//   row loads are interleaved -> 32 loads in flight per warp. 4096 warps total
//   -> single wave on 148 SMs (no second-wave tail). Closed-form Pearson from
//   5 sums per patch; block partials -> last-block final reduction.

#define W_IMG 4096
#define BOX   32
#define PATCH 1024.0f
#define MAX_BLOCKS 8192

__device__ float        g_partials[MAX_BLOCKS];
__device__ unsigned int g_done = 0;

__device__ __forceinline__ float pearson_contrib(
    float sp, float sg, float spp, float sgg, float spg, float inv_n)
{
    const float P = PATCH;
    float mp = sp / P;
    float mg = sg / P;
    float varp = (spp - P * mp * mp) * (1.0f / (P - 1.0f));
    float varg = (sgg - P * mg * mg) * (1.0f / (P - 1.0f));
    float stdp = sqrtf(fmaxf(varp, 0.0f)) + 1e-6f;
    float stdg = sqrtf(fmaxf(varg, 0.0f)) + 1e-6f;
    float cov = spg / P - mp * mg;
    return (1.0f - cov / (stdp * stdg)) * inv_n;
}

__global__ __launch_bounds__(256) void pearson_loss_kernel(
    const float* __restrict__ pred,
    const float* __restrict__ gt,
    const int*   __restrict__ x0,
    const int*   __restrict__ y0,
    float* __restrict__ out,
    int n_corr)
{
    const int warp_global = (blockIdx.x * blockDim.x + threadIdx.x) >> 5;
    const int lane = threadIdx.x & 31;
    const int wid_in_blk = threadIdx.x >> 5;

    const int iA = warp_global * 2;
    const int iB = iA + 1;
    const bool hasA = (iA < n_corr);
    const bool hasB = (iB < n_corr);

    float contrib = 0.0f;

    if (hasA) {
        const int xa = x0[iA], ya = y0[iA];
        // If no second patch, alias B to A (loads are harmless, contrib masked).
        const int xb = hasB ? x0[iB] : xa;
        const int yb = hasB ? y0[iB] : ya;

        const float* __restrict__ pA = pred + (size_t)xa * W_IMG + ya + lane;
        const float* __restrict__ gA = gt   + (size_t)xa * W_IMG + ya + lane;
        const float* __restrict__ pB = pred + (size_t)xb * W_IMG + yb + lane;
        const float* __restrict__ gB = gt   + (size_t)xb * W_IMG + yb + lane;

        float spA = 0.f, sgA = 0.f, sppA = 0.f, sggA = 0.f, spgA = 0.f;
        float spB = 0.f, sgB = 0.f, sppB = 0.f, sggB = 0.f, spgB = 0.f;

        #pragma unroll
        for (int rb = 0; rb < BOX / 8; rb++) {
            float pa[8], ga[8], pb[8], gb[8];
            #pragma unroll
            for (int i = 0; i < 8; i++) {
                const size_t off = (size_t)(rb * 8 + i) * W_IMG;
                pa[i] = __ldg(pA + off);
                ga[i] = __ldg(gA + off);
                pb[i] = __ldg(pB + off);
                gb[i] = __ldg(gB + off);
            }
            #pragma unroll
            for (int i = 0; i < 8; i++) {
                spA  += pa[i];
                sgA  += ga[i];
                sppA = fmaf(pa[i], pa[i], sppA);
                sggA = fmaf(ga[i], ga[i], sggA);
                spgA = fmaf(pa[i], ga[i], spgA);
                spB  += pb[i];
                sgB  += gb[i];
                sppB = fmaf(pb[i], pb[i], sppB);
                sggB = fmaf(gb[i], gb[i], sggB);
                spgB = fmaf(pb[i], gb[i], spgB);
            }
        }

        #pragma unroll
        for (int off = 16; off > 0; off >>= 1) {
            spA  += __shfl_xor_sync(0xffffffffu, spA,  off);
            sgA  += __shfl_xor_sync(0xffffffffu, sgA,  off);
            sppA += __shfl_xor_sync(0xffffffffu, sppA, off);
            sggA += __shfl_xor_sync(0xffffffffu, sggA, off);
            spgA += __shfl_xor_sync(0xffffffffu, spgA, off);
            spB  += __shfl_xor_sync(0xffffffffu, spB,  off);
            sgB  += __shfl_xor_sync(0xffffffffu, sgB,  off);
            sppB += __shfl_xor_sync(0xffffffffu, sppB, off);
            sggB += __shfl_xor_sync(0xffffffffu, sggB, off);
            spgB += __shfl_xor_sync(0xffffffffu, spgB, off);
        }

        if (lane == 0) {
            const float inv_n = 1.0f / (float)n_corr;
            contrib = pearson_contrib(spA, sgA, sppA, sggA, spgA, inv_n);
            if (hasB)
                contrib += pearson_contrib(spB, sgB, sppB, sggB, spgB, inv_n);
        }
    }

    // Block reduce warp contributions.
    __shared__ float warp_sums[8];
    __shared__ bool  is_last;
    if (lane == 0) warp_sums[wid_in_blk] = contrib;
    __syncthreads();
    if (threadIdx.x == 0) {
        float bs = 0.0f;
        #pragma unroll
        for (int w = 0; w < 8; w++) bs += warp_sums[w];
        g_partials[blockIdx.x] = bs;
        __threadfence();                       // release our partial
        unsigned int old = atomicAdd(&g_done, 1u);
        is_last = (old == gridDim.x - 1);
        if (is_last) __threadfence();          // acquire all partials
    }
    __syncthreads();

    if (is_last) {
        float v = 0.0f;
        for (int i = threadIdx.x; i < gridDim.x; i += blockDim.x)
            v += g_partials[i];
        #pragma unroll
        for (int off = 16; off > 0; off >>= 1)
            v += __shfl_xor_sync(0xffffffffu, v, off);
        if (lane == 0) warp_sums[wid_in_blk] = v;
        __syncthreads();
        if (threadIdx.x == 0) {
            float total = 0.0f;
            #pragma unroll
            for (int w = 0; w < 8; w++) total += warp_sums[w];
            out[0] = total;
            g_done = 0;   // reset for next graph replay
        }
    }
}

extern "C" void kernel_launch(void* const* d_in, const int* in_sizes, int n_in,
                              void* d_out, int out_size)
{
    const float* pred = (const float*)d_in[0];
    const float* gt   = (const float*)d_in[1];
    const int*   x0   = (const int*)d_in[2];
    const int*   y0   = (const int*)d_in[3];
    float* out = (float*)d_out;

    const int n_corr = in_sizes[2];

    const int threads = 256;                     // 8 warps/block, 2 patches/warp
    const int patches_per_blk = (threads / 32) * 2;
    const int blocks = (n_corr + patches_per_blk - 1) / patches_per_blk;
    pearson_loss_kernel<<<blocks, threads>>>(pred, gt, x0, y0, out, n_corr);
}